// round 7
// baseline (speedup 1.0000x reference)
#include <cuda_runtime.h>
#include <cuda_bf16.h>
#include <math.h>
#include <stdint.h>

#define BB 4
#define NN 2048
#define DIM 768
#define NH 12
#define HD 64
#define MROWS (BB*NN)   // 8192

// Scratch: q,k,v in [b,h,n,d] layout
__device__ float g_q[BB*NH*NN*HD];
__device__ float g_k[BB*NH*NN*HD];
__device__ float g_v[BB*NH*NN*HD];

// ====================== mma.sync helpers (family-portable) ======================
__device__ __forceinline__ uint32_t smem_u32(const void* p) {
    uint32_t a;
    asm("{ .reg .u64 t; cvta.to.shared.u64 t, %1; cvt.u32.u64 %0, t; }"
        : "=r"(a) : "l"(p));
    return a;
}

__device__ __forceinline__ void ldm_x4(uint32_t* r, uint32_t addr) {
    asm volatile("ldmatrix.sync.aligned.m8n8.x4.shared.b16 {%0,%1,%2,%3}, [%4];"
                 : "=r"(r[0]), "=r"(r[1]), "=r"(r[2]), "=r"(r[3]) : "r"(addr));
}

__device__ __forceinline__ void mma_bf16(float* c, const uint32_t* a,
                                         uint32_t b0, uint32_t b1) {
    asm volatile(
        "mma.sync.aligned.m16n8k16.row.col.f32.bf16.bf16.f32 "
        "{%0,%1,%2,%3}, {%4,%5,%6,%7}, {%8,%9}, {%0,%1,%2,%3};"
        : "+f"(c[0]), "+f"(c[1]), "+f"(c[2]), "+f"(c[3])
        : "r"(a[0]), "r"(a[1]), "r"(a[2]), "r"(a[3]), "r"(b0), "r"(b1));
}

__device__ __forceinline__ uint32_t pk_bf2(__nv_bfloat16 a, __nv_bfloat16 b) {
    __nv_bfloat162 t(a, b);
    uint32_t u; *(__nv_bfloat162*)&u = t; return u;
}

__device__ __forceinline__ void cvt_hilo(float4 v, uint2& hi, uint2& lo) {
    __nv_bfloat16 h0 = __float2bfloat16(v.x), h1 = __float2bfloat16(v.y),
                  h2 = __float2bfloat16(v.z), h3 = __float2bfloat16(v.w);
    __nv_bfloat16 l0 = __float2bfloat16(v.x - __bfloat162float(h0));
    __nv_bfloat16 l1 = __float2bfloat16(v.y - __bfloat162float(h1));
    __nv_bfloat16 l2 = __float2bfloat16(v.z - __bfloat162float(h2));
    __nv_bfloat16 l3 = __float2bfloat16(v.w - __bfloat162float(h3));
    hi = make_uint2(pk_bf2(h0, h1), pk_bf2(h2, h3));
    lo = make_uint2(pk_bf2(l0, l1), pk_bf2(l2, l3));
}

// ===================== QKV GEMM via mma.sync bf16 hi/lo =====================
// Y[m][o] = sum_k X[m][k]*W[o][k] + b[o].  CTA tile 128x128, K chunks of 64.
// smem tiles: 128 rows x 64 bf16, row pitch 72 elems (144B) -> ldmatrix conflict-free.
#define CH  64
#define RP  72                    // bf16 elems per row
#define RPB 144                   // bytes per row
#define TILEB (128*RPB)           // 18432 B per tile

__global__ __launch_bounds__(256) void qkv_mma(
    const float* __restrict__ x,
    const float* __restrict__ wq, const float* __restrict__ bq,
    const float* __restrict__ wk, const float* __restrict__ bk,
    const float* __restrict__ wv, const float* __restrict__ bv)
{
    extern __shared__ char smem[];
    char* Ahi = smem;
    char* Alo = Ahi + TILEB;
    char* Bhi = Alo + TILEB;
    char* Blo = Bhi + TILEB;
    const uint32_t sA_hi = smem_u32(Ahi);
    const uint32_t sA_lo = sA_hi + TILEB;
    const uint32_t sB_hi = sA_lo + TILEB;
    const uint32_t sB_lo = sB_hi + TILEB;

    const int mat = blockIdx.z;
    const float* w    = (mat == 0) ? wq : (mat == 1) ? wk : wv;
    const float* bias = (mat == 0) ? bq : (mat == 1) ? bk : bv;
    float* dst        = (mat == 0) ? g_q : (mat == 1) ? g_k : g_v;

    const int m0 = blockIdx.y * 128;
    const int o0 = blockIdx.x * 128;
    const int tid = threadIdx.x;
    const int wid = tid >> 5, lane = tid & 31;
    const int warpM = wid & 3, warpN = wid >> 2;   // 4x2 warp grid
    const int m0w = warpM * 32, n0w = warpN * 64;

    // ldmatrix per-lane address offset (canonical x4 pattern):
    // lanes 0-15 -> rows 0-15 @ +0B, lanes 16-31 -> rows 0-15 @ +16B
    const uint32_t lm_off = (uint32_t)(lane & 15) * RPB + (uint32_t)(lane >> 4) * 16;

    float acc[2][8][4];
#pragma unroll
    for (int mt = 0; mt < 2; mt++)
#pragma unroll
        for (int nt = 0; nt < 8; nt++)
#pragma unroll
            for (int q = 0; q < 4; q++) acc[mt][nt][q] = 0.f;

    for (int c = 0; c < DIM / CH; ++c) {      // 12 chunks
        const int kb = c * CH;
        __syncthreads();
        // Load + convert chunk: 128 rows x 64 cols per operand, 8 float4/thread each
#pragma unroll
        for (int p = 0; p < 8; ++p) {
            int e = tid + p * 256;
            int row = e >> 4, k4 = e & 15;
            uint32_t off = (uint32_t)(row * RPB + k4 * 8);
            uint2 hi, lo;
            cvt_hilo(*(const float4*)(x + (size_t)(m0 + row) * DIM + kb + 4 * k4), hi, lo);
            *(uint2*)(Ahi + off) = hi;
            *(uint2*)(Alo + off) = lo;
            cvt_hilo(*(const float4*)(w + (size_t)(o0 + row) * DIM + kb + 4 * k4), hi, lo);
            *(uint2*)(Bhi + off) = hi;
            *(uint2*)(Blo + off) = lo;
        }
        __syncthreads();

#pragma unroll
        for (int ks = 0; ks < 4; ++ks) {      // 4 x k16 = 64
            const uint32_t kso = (uint32_t)ks * 32;
            uint32_t a_hi[2][4], a_lo[2][4];
#pragma unroll
            for (int mt = 0; mt < 2; mt++) {
                uint32_t base = (uint32_t)(m0w + 16 * mt) * RPB + kso + lm_off;
                ldm_x4(a_hi[mt], sA_hi + base);
                ldm_x4(a_lo[mt], sA_lo + base);
            }
#pragma unroll
            for (int bp = 0; bp < 4; bp++) {  // 16 n-rows per ldmatrix.x4
                uint32_t base = (uint32_t)(n0w + 16 * bp) * RPB + kso + lm_off;
                uint32_t b_hi[4], b_lo[4];
                ldm_x4(b_hi, sB_hi + base);
                ldm_x4(b_lo, sB_lo + base);
                // n-tile 2*bp   frag = {r0, r2};  n-tile 2*bp+1 frag = {r1, r3}
#pragma unroll
                for (int half = 0; half < 2; half++) {
                    int nt = 2 * bp + half;
#pragma unroll
                    for (int mt = 0; mt < 2; mt++) {
                        mma_bf16(acc[mt][nt], a_hi[mt], b_hi[half], b_hi[half + 2]);
                        mma_bf16(acc[mt][nt], a_hi[mt], b_lo[half], b_lo[half + 2]);
                        mma_bf16(acc[mt][nt], a_lo[mt], b_hi[half], b_hi[half + 2]);
                    }
                }
            }
        }
    }

    // Epilogue: bias add + head-split store [b,h,n,d].
    // Accum map (m16n8): c0,c1 -> row lane>>2, cols 2*(lane&3)+{0,1}; c2,c3 -> row+8.
#pragma unroll
    for (int mt = 0; mt < 2; mt++) {
#pragma unroll
        for (int nt = 0; nt < 8; nt++) {
            int row0 = m0 + m0w + 16 * mt + (lane >> 2);
            int col  = o0 + n0w + 8 * nt + 2 * (lane & 3);
            int h = col / HD, d = col & (HD - 1);
            float b0 = bias[col], b1 = bias[col + 1];
            {
                int b_ = row0 >> 11, n = row0 & (NN - 1);
                float2 v = make_float2(acc[mt][nt][0] + b0, acc[mt][nt][1] + b1);
                *(float2*)&dst[(((size_t)b_ * NH + h) * NN + n) * HD + d] = v;
            }
            {
                int row1 = row0 + 8;
                int b_ = row1 >> 11, n = row1 & (NN - 1);
                float2 v = make_float2(acc[mt][nt][2] + b0, acc[mt][nt][3] + b1);
                *(float2*)&dst[(((size_t)b_ * NH + h) * NN + n) * HD + d] = v;
            }
        }
    }
}

// =====================  Flash attention (unchanged from R4)  =====================
#define QT 128
#define KT 64
#define QP 132
#define KP 68

__global__ __launch_bounds__(256) void attn_kernel(float* __restrict__ out)
{
    extern __shared__ float sm[];
    float* Qt = sm;
    float* Kt = Qt + 64 * QP;
    float* Vs = Kt + 64 * KP;
    float* Pt = Vs + 64 * KP;

    const int b = blockIdx.z, h = blockIdx.y;
    const int q0 = blockIdx.x * QT;
    const size_t hb = ((size_t)b * NH + h) * NN;
    const float* qbase = g_q + hb * HD;
    const float* kbase = g_k + hb * HD;
    const float* vbase = g_v + hb * HD;

    const int tid = threadIdx.x;
    const int ty = tid >> 4, tx = tid & 15;

#pragma unroll
    for (int p = 0; p < 8; p++) {
        int e = tid + p * 256;
        int row = e >> 4, d4 = e & 15;
        float4 v = *(const float4*)(qbase + (size_t)(q0 + row) * HD + 4 * d4);
        Qt[(4*d4+0) * QP + row] = v.x;
        Qt[(4*d4+1) * QP + row] = v.y;
        Qt[(4*d4+2) * QP + row] = v.z;
        Qt[(4*d4+3) * QP + row] = v.w;
    }

    float o_acc[8][4];
    float mrow[8], lrow[8];
#pragma unroll
    for (int i = 0; i < 8; i++) {
        mrow[i] = -INFINITY; lrow[i] = 0.f;
#pragma unroll
        for (int j = 0; j < 4; j++) o_acc[i][j] = 0.f;
    }

    for (int j0 = 0; j0 < NN; j0 += KT) {
        __syncthreads();
#pragma unroll
        for (int p = 0; p < 4; p++) {
            int e = tid + p * 256;
            int kv = e >> 4, d4 = e & 15;
            float4 kvec = *(const float4*)(kbase + (size_t)(j0 + kv) * HD + 4 * d4);
            Kt[(4*d4+0) * KP + kv] = kvec.x;
            Kt[(4*d4+1) * KP + kv] = kvec.y;
            Kt[(4*d4+2) * KP + kv] = kvec.z;
            Kt[(4*d4+3) * KP + kv] = kvec.w;
            float4 vvec = *(const float4*)(vbase + (size_t)(j0 + kv) * HD + 4 * d4);
            *(float4*)&Vs[kv * KP + 4 * d4] = vvec;
        }
        __syncthreads();

        float s[8][4];
#pragma unroll
        for (int i = 0; i < 8; i++)
#pragma unroll
            for (int j = 0; j < 4; j++) s[i][j] = 0.f;

#pragma unroll 4
        for (int kk = 0; kk < 64; kk++) {
            float a[8], bv4[4];
            *(float4*)(a)     = *(const float4*)&Qt[kk * QP + 8 * ty];
            *(float4*)(a + 4) = *(const float4*)&Qt[kk * QP + 8 * ty + 4];
            *(float4*)(bv4)   = *(const float4*)&Kt[kk * KP + 4 * tx];
#pragma unroll
            for (int i = 0; i < 8; i++)
#pragma unroll
                for (int j = 0; j < 4; j++)
                    s[i][j] = fmaf(a[i], bv4[j], s[i][j]);
        }

#pragma unroll
        for (int i = 0; i < 8; i++) {
            float mloc = -INFINITY;
#pragma unroll
            for (int j = 0; j < 4; j++) {
                s[i][j] *= 0.125f;
                mloc = fmaxf(mloc, s[i][j]);
            }
#pragma unroll
            for (int off = 8; off >= 1; off >>= 1)
                mloc = fmaxf(mloc, __shfl_xor_sync(0xffffffffu, mloc, off));
            float mnew = fmaxf(mrow[i], mloc);
            float alpha = __expf(mrow[i] - mnew);
            float rsum = 0.f;
#pragma unroll
            for (int j = 0; j < 4; j++) {
                s[i][j] = __expf(s[i][j] - mnew);
                rsum += s[i][j];
            }
#pragma unroll
            for (int off = 8; off >= 1; off >>= 1)
                rsum += __shfl_xor_sync(0xffffffffu, rsum, off);
            lrow[i] = lrow[i] * alpha + rsum;
            mrow[i] = mnew;
#pragma unroll
            for (int j = 0; j < 4; j++) o_acc[i][j] *= alpha;
        }

#pragma unroll
        for (int j = 0; j < 4; j++) {
            float4 v0 = make_float4(s[0][j], s[1][j], s[2][j], s[3][j]);
            float4 v1 = make_float4(s[4][j], s[5][j], s[6][j], s[7][j]);
            float* p = &Pt[(4 * tx + j) * QP + 8 * ty];
            *(float4*)(p)     = v0;
            *(float4*)(p + 4) = v1;
        }
        __syncthreads();

#pragma unroll 4
        for (int k = 0; k < 64; k++) {
            float a[8], bv4[4];
            *(float4*)(a)     = *(const float4*)&Pt[k * QP + 8 * ty];
            *(float4*)(a + 4) = *(const float4*)&Pt[k * QP + 8 * ty + 4];
            *(float4*)(bv4)   = *(const float4*)&Vs[k * KP + 4 * tx];
#pragma unroll
            for (int i = 0; i < 8; i++)
#pragma unroll
                for (int j = 0; j < 4; j++)
                    o_acc[i][j] = fmaf(a[i], bv4[j], o_acc[i][j]);
        }
    }

#pragma unroll
    for (int i = 0; i < 8; i++) {
        float inv = 1.f / lrow[i];
        int n = q0 + 8 * ty + i;
        float4 o4 = make_float4(o_acc[i][0] * inv, o_acc[i][1] * inv,
                                o_acc[i][2] * inv, o_acc[i][3] * inv);
        *(float4*)&out[((size_t)b * NN + n) * DIM + h * HD + 4 * tx] = o4;
    }
}

extern "C" void kernel_launch(void* const* d_in, const int* in_sizes, int n_in,
                              void* d_out, int out_size)
{
    (void)in_sizes; (void)n_in; (void)out_size;
    const float* x  = (const float*)d_in[0];
    const float* wq = (const float*)d_in[1];
    const float* bq = (const float*)d_in[2];
    const float* wk = (const float*)d_in[3];
    const float* bk = (const float*)d_in[4];
    const float* wv = (const float*)d_in[5];
    const float* bv = (const float*)d_in[6];
    float* out = (float*)d_out;

    // QKV via mma.sync: grid (6 n-tiles, 64 m-tiles, 3 matrices)
    size_t q_smem = 4 * (size_t)TILEB;   // 73728 B
    cudaFuncSetAttribute(qkv_mma, cudaFuncAttributeMaxDynamicSharedMemorySize,
                         (int)q_smem);
    dim3 g1(DIM / 128, MROWS / 128, 3);
    qkv_mma<<<g1, 256, q_smem>>>(x, wq, bq, wk, bk, wv, bv);

    size_t smem = (size_t)(64 * QP * 2 + 64 * KP * 2) * sizeof(float);
    cudaFuncSetAttribute(attn_kernel, cudaFuncAttributeMaxDynamicSharedMemorySize,
                         (int)smem);
    dim3 g2(NN / QT, NH, BB);
    attn_kernel<<<g2, 256, smem>>>(out);
}

// round 8
// speedup vs baseline: 3.0802x; 3.0802x over previous
#include <cuda_runtime.h>
#include <cuda_bf16.h>
#include <math.h>
#include <stdint.h>

#define BB 4
#define NN 2048
#define DIM 768
#define NH 12
#define HD 64
#define MROWS (BB*NN)   // 8192

// Scratch: q,k,v in [b,h,n,d] layout
__device__ float g_q[BB*NH*NN*HD];
__device__ float g_k[BB*NH*NN*HD];
__device__ float g_v[BB*NH*NN*HD];

// ====================== mma.sync helpers ======================
__device__ __forceinline__ uint32_t smem_u32(const void* p) {
    uint32_t a;
    asm("{ .reg .u64 t; cvta.to.shared.u64 t, %1; cvt.u32.u64 %0, t; }"
        : "=r"(a) : "l"(p));
    return a;
}
__device__ __forceinline__ void ldm_x4(uint32_t* r, uint32_t addr) {
    asm volatile("ldmatrix.sync.aligned.m8n8.x4.shared.b16 {%0,%1,%2,%3}, [%4];"
                 : "=r"(r[0]), "=r"(r[1]), "=r"(r[2]), "=r"(r[3]) : "r"(addr));
}
__device__ __forceinline__ void ldm_x4_t(uint32_t* r, uint32_t addr) {
    asm volatile("ldmatrix.sync.aligned.m8n8.x4.trans.shared.b16 {%0,%1,%2,%3}, [%4];"
                 : "=r"(r[0]), "=r"(r[1]), "=r"(r[2]), "=r"(r[3]) : "r"(addr));
}
__device__ __forceinline__ void mma_bf16(float* c, const uint32_t* a,
                                         uint32_t b0, uint32_t b1) {
    asm volatile(
        "mma.sync.aligned.m16n8k16.row.col.f32.bf16.bf16.f32 "
        "{%0,%1,%2,%3}, {%4,%5,%6,%7}, {%8,%9}, {%0,%1,%2,%3};"
        : "+f"(c[0]), "+f"(c[1]), "+f"(c[2]), "+f"(c[3])
        : "r"(a[0]), "r"(a[1]), "r"(a[2]), "r"(a[3]), "r"(b0), "r"(b1));
}
__device__ __forceinline__ uint32_t pk_bf2(__nv_bfloat16 a, __nv_bfloat16 b) {
    __nv_bfloat162 t(a, b);
    uint32_t u; *(__nv_bfloat162*)&u = t; return u;
}
// pack (lo elem, hi elem) -> bf16x2
__device__ __forceinline__ uint32_t pk_lohi(float lo, float hi) {
    uint32_t r;
    asm("cvt.rn.bf16x2.f32 %0, %1, %2;" : "=r"(r) : "f"(hi), "f"(lo));
    return r;
}
__device__ __forceinline__ float ex2f(float x) {
    float y;
    asm("ex2.approx.ftz.f32 %0, %1;" : "=f"(y) : "f"(x));
    return y;
}
__device__ __forceinline__ void cvt_hilo(float4 v, uint2& hi, uint2& lo) {
    __nv_bfloat16 h0 = __float2bfloat16(v.x), h1 = __float2bfloat16(v.y),
                  h2 = __float2bfloat16(v.z), h3 = __float2bfloat16(v.w);
    __nv_bfloat16 l0 = __float2bfloat16(v.x - __bfloat162float(h0));
    __nv_bfloat16 l1 = __float2bfloat16(v.y - __bfloat162float(h1));
    __nv_bfloat16 l2 = __float2bfloat16(v.z - __bfloat162float(h2));
    __nv_bfloat16 l3 = __float2bfloat16(v.w - __bfloat162float(h3));
    hi = make_uint2(pk_bf2(h0, h1), pk_bf2(h2, h3));
    lo = make_uint2(pk_bf2(l0, l1), pk_bf2(l2, l3));
}

#define RP  72
#define RPB 144
#define TILEB (128*RPB)           // 18432 B (128-row tile)
#define KTILEB (64*RPB)           // 9216 B  (64-row tile)

// ===================== QKV GEMM via mma.sync bf16 hi/lo (validated R7) =====================
#define CH 64

__global__ __launch_bounds__(256) void qkv_mma(
    const float* __restrict__ x,
    const float* __restrict__ wq, const float* __restrict__ bq,
    const float* __restrict__ wk, const float* __restrict__ bk,
    const float* __restrict__ wv, const float* __restrict__ bv)
{
    extern __shared__ char smem[];
    char* Ahi = smem;
    char* Alo = Ahi + TILEB;
    char* Bhi = Alo + TILEB;
    char* Blo = Bhi + TILEB;
    const uint32_t sA_hi = smem_u32(Ahi);
    const uint32_t sA_lo = sA_hi + TILEB;
    const uint32_t sB_hi = sA_lo + TILEB;
    const uint32_t sB_lo = sB_hi + TILEB;

    const int mat = blockIdx.z;
    const float* w    = (mat == 0) ? wq : (mat == 1) ? wk : wv;
    const float* bias = (mat == 0) ? bq : (mat == 1) ? bk : bv;
    float* dst        = (mat == 0) ? g_q : (mat == 1) ? g_k : g_v;

    const int m0 = blockIdx.y * 128;
    const int o0 = blockIdx.x * 128;
    const int tid = threadIdx.x;
    const int wid = tid >> 5, lane = tid & 31;
    const int warpM = wid & 3, warpN = wid >> 2;
    const int m0w = warpM * 32, n0w = warpN * 64;
    const uint32_t lm_off = (uint32_t)(lane & 15) * RPB + (uint32_t)(lane >> 4) * 16;

    float acc[2][8][4];
#pragma unroll
    for (int mt = 0; mt < 2; mt++)
#pragma unroll
        for (int nt = 0; nt < 8; nt++)
#pragma unroll
            for (int q = 0; q < 4; q++) acc[mt][nt][q] = 0.f;

    for (int c = 0; c < DIM / CH; ++c) {
        const int kb = c * CH;
        __syncthreads();
#pragma unroll
        for (int p = 0; p < 8; ++p) {
            int e = tid + p * 256;
            int row = e >> 4, k4 = e & 15;
            uint32_t off = (uint32_t)(row * RPB + k4 * 8);
            uint2 hi, lo;
            cvt_hilo(*(const float4*)(x + (size_t)(m0 + row) * DIM + kb + 4 * k4), hi, lo);
            *(uint2*)(Ahi + off) = hi;
            *(uint2*)(Alo + off) = lo;
            cvt_hilo(*(const float4*)(w + (size_t)(o0 + row) * DIM + kb + 4 * k4), hi, lo);
            *(uint2*)(Bhi + off) = hi;
            *(uint2*)(Blo + off) = lo;
        }
        __syncthreads();

#pragma unroll
        for (int ks = 0; ks < 4; ++ks) {
            const uint32_t kso = (uint32_t)ks * 32;
            uint32_t a_hi[2][4], a_lo[2][4];
#pragma unroll
            for (int mt = 0; mt < 2; mt++) {
                uint32_t base = (uint32_t)(m0w + 16 * mt) * RPB + kso + lm_off;
                ldm_x4(a_hi[mt], sA_hi + base);
                ldm_x4(a_lo[mt], sA_lo + base);
            }
#pragma unroll
            for (int bp = 0; bp < 4; bp++) {
                uint32_t base = (uint32_t)(n0w + 16 * bp) * RPB + kso + lm_off;
                uint32_t b_hi[4], b_lo[4];
                ldm_x4(b_hi, sB_hi + base);
                ldm_x4(b_lo, sB_lo + base);
#pragma unroll
                for (int half = 0; half < 2; half++) {
                    int nt = 2 * bp + half;
#pragma unroll
                    for (int mt = 0; mt < 2; mt++) {
                        mma_bf16(acc[mt][nt], a_hi[mt], b_hi[half], b_hi[half + 2]);
                        mma_bf16(acc[mt][nt], a_hi[mt], b_lo[half], b_lo[half + 2]);
                        mma_bf16(acc[mt][nt], a_lo[mt], b_hi[half], b_hi[half + 2]);
                    }
                }
            }
        }
    }

#pragma unroll
    for (int mt = 0; mt < 2; mt++) {
#pragma unroll
        for (int nt = 0; nt < 8; nt++) {
            int row0 = m0 + m0w + 16 * mt + (lane >> 2);
            int col  = o0 + n0w + 8 * nt + 2 * (lane & 3);
            int h = col / HD, d = col & (HD - 1);
            float b0 = bias[col], b1 = bias[col + 1];
            {
                int b_ = row0 >> 11, n = row0 & (NN - 1);
                float2 v = make_float2(acc[mt][nt][0] + b0, acc[mt][nt][1] + b1);
                *(float2*)&dst[(((size_t)b_ * NH + h) * NN + n) * HD + d] = v;
            }
            {
                int row1 = row0 + 8;
                int b_ = row1 >> 11, n = row1 & (NN - 1);
                float2 v = make_float2(acc[mt][nt][2] + b0, acc[mt][nt][3] + b1);
                *(float2*)&dst[(((size_t)b_ * NH + h) * NN + n) * HD + d] = v;
            }
        }
    }
}

// ===================== Flash attention via mma.sync bf16 hi/lo =====================
// CTA: (b, h, 128 Q rows). 8 warps x 16 rows. KV tiles of 64.
// Q scaled by 0.125*log2e at load; softmax in log2 domain (ex2.approx).
// P stays in registers (C-frag -> A-frag repack); V via ldmatrix.trans.
__global__ __launch_bounds__(256) void attn_mma(float* __restrict__ out)
{
    extern __shared__ char smem[];
    char* Qhi = smem;                   //  [128][RP] bf16
    char* Qlo = Qhi + TILEB;
    char* Khi = Qlo + TILEB;            //  [64][RP]
    char* Klo = Khi + KTILEB;
    char* Vhi = Klo + KTILEB;           //  [64][RP] natural [kv][d]
    char* Vlo = Vhi + KTILEB;
    const uint32_t sQhi = smem_u32(Qhi);
    const uint32_t sQlo = sQhi + TILEB;
    const uint32_t sKhi = sQlo + TILEB;
    const uint32_t sKlo = sKhi + KTILEB;
    const uint32_t sVhi = sKlo + KTILEB;
    const uint32_t sVlo = sVhi + KTILEB;

    const int b = blockIdx.z, h = blockIdx.y;
    const int q0 = blockIdx.x * 128;
    const size_t hb = ((size_t)b * NH + h) * NN;
    const float* qbase = g_q + hb * HD;
    const float* kbase = g_k + hb * HD;
    const float* vbase = g_v + hb * HD;

    const int tid = threadIdx.x;
    const int wid = tid >> 5, lane = tid & 31;
    const uint32_t lm_off = (uint32_t)(lane & 15) * RPB + (uint32_t)(lane >> 4) * 16;
    const float qsc = 0.125f * 1.44269504f;   // headdim^-0.5 * log2(e)

    // Load Q (scaled) -> hi/lo smem: 128x64, 8 float4/thread
#pragma unroll
    for (int p = 0; p < 8; ++p) {
        int e = tid + p * 256;
        int row = e >> 4, k4 = e & 15;
        float4 v = *(const float4*)(qbase + (size_t)(q0 + row) * HD + 4 * k4);
        v.x *= qsc; v.y *= qsc; v.z *= qsc; v.w *= qsc;
        uint2 hi, lo;
        cvt_hilo(v, hi, lo);
        uint32_t off = (uint32_t)(row * RPB + k4 * 8);
        *(uint2*)(Qhi + off) = hi;
        *(uint2*)(Qlo + off) = lo;
    }

    float o_[8][4];
    float mA = -INFINITY, mB = -INFINITY, lA = 0.f, lB = 0.f;
#pragma unroll
    for (int nt = 0; nt < 8; nt++)
#pragma unroll
        for (int q = 0; q < 4; q++) o_[nt][q] = 0.f;

    for (int j0 = 0; j0 < NN; j0 += 64) {
        __syncthreads();   // prior-iter V reads done before overwrite
#pragma unroll
        for (int p = 0; p < 4; ++p) {
            int e = tid + p * 256;
            int kv = e >> 4, d4 = e & 15;
            uint32_t off = (uint32_t)(kv * RPB + d4 * 8);
            uint2 hi, lo;
            cvt_hilo(*(const float4*)(kbase + (size_t)(j0 + kv) * HD + 4 * d4), hi, lo);
            *(uint2*)(Khi + off) = hi;
            *(uint2*)(Klo + off) = lo;
            cvt_hilo(*(const float4*)(vbase + (size_t)(j0 + kv) * HD + 4 * d4), hi, lo);
            *(uint2*)(Vhi + off) = hi;
            *(uint2*)(Vlo + off) = lo;
        }
        __syncthreads();

        // ---- S = Qs @ K^T (log2-domain logits), 3-term hi/lo ----
        float s_[8][4];
#pragma unroll
        for (int nt = 0; nt < 8; nt++)
#pragma unroll
            for (int q = 0; q < 4; q++) s_[nt][q] = 0.f;

#pragma unroll
        for (int ks = 0; ks < 4; ++ks) {
            const uint32_t kso = (uint32_t)ks * 32;
            uint32_t ah[4], al[4];
            uint32_t ab = (uint32_t)(wid * 16) * RPB + kso + lm_off;
            ldm_x4(ah, sQhi + ab);
            ldm_x4(al, sQlo + ab);
#pragma unroll
            for (int bp = 0; bp < 4; bp++) {
                uint32_t bb = (uint32_t)(16 * bp) * RPB + kso + lm_off;
                uint32_t bh[4], bl[4];
                ldm_x4(bh, sKhi + bb);
                ldm_x4(bl, sKlo + bb);
#pragma unroll
                for (int half = 0; half < 2; half++) {
                    int nt = 2 * bp + half;
                    mma_bf16(s_[nt], ah, bh[half], bh[half + 2]);
                    mma_bf16(s_[nt], ah, bl[half], bl[half + 2]);
                    mma_bf16(s_[nt], al, bh[half], bh[half + 2]);
                }
            }
        }

        // ---- online softmax (rows rA = lane>>2, rB = rA+8) ----
        float mlA = -INFINITY, mlB = -INFINITY;
#pragma unroll
        for (int nt = 0; nt < 8; nt++) {
            mlA = fmaxf(mlA, fmaxf(s_[nt][0], s_[nt][1]));
            mlB = fmaxf(mlB, fmaxf(s_[nt][2], s_[nt][3]));
        }
#pragma unroll
        for (int off = 1; off <= 2; off <<= 1) {
            mlA = fmaxf(mlA, __shfl_xor_sync(0xffffffffu, mlA, off));
            mlB = fmaxf(mlB, __shfl_xor_sync(0xffffffffu, mlB, off));
        }
        float mnA = fmaxf(mA, mlA), mnB = fmaxf(mB, mlB);
        float aAl = ex2f(mA - mnA), aBl = ex2f(mB - mnB);
        mA = mnA; mB = mnB;
        float sumA = 0.f, sumB = 0.f;
#pragma unroll
        for (int nt = 0; nt < 8; nt++) {
            s_[nt][0] = ex2f(s_[nt][0] - mA);
            s_[nt][1] = ex2f(s_[nt][1] - mA);
            s_[nt][2] = ex2f(s_[nt][2] - mB);
            s_[nt][3] = ex2f(s_[nt][3] - mB);
            sumA += s_[nt][0] + s_[nt][1];
            sumB += s_[nt][2] + s_[nt][3];
            o_[nt][0] *= aAl; o_[nt][1] *= aAl;
            o_[nt][2] *= aBl; o_[nt][3] *= aBl;
        }
#pragma unroll
        for (int off = 1; off <= 2; off <<= 1) {
            sumA += __shfl_xor_sync(0xffffffffu, sumA, off);
            sumB += __shfl_xor_sync(0xffffffffu, sumB, off);
        }
        lA = lA * aAl + sumA;
        lB = lB * aBl + sumB;

        // ---- O += P @ V : P repacked C-frag -> A-frag, V via ldmatrix.trans ----
#pragma unroll
        for (int t = 0; t < 4; t++) {
            uint32_t pah[4], pal[4];
#pragma unroll
            for (int i = 0; i < 4; i++) {
                const float* src = (i < 2) ? s_[2 * t] : s_[2 * t + 1];
                float x0 = src[(i & 1) ? 2 : 0];
                float x1 = src[(i & 1) ? 3 : 1];
                float h0 = __bfloat162float(__float2bfloat16(x0));
                float h1 = __bfloat162float(__float2bfloat16(x1));
                pah[i] = pk_lohi(h0, h1);
                pal[i] = pk_lohi(x0 - h0, x1 - h1);
            }
#pragma unroll
            for (int db = 0; db < 4; db++) {
                // trans ldmatrix: tiles (kv0-7,d0-7),(kv8-15,d0-7),(kv0-7,d8-15),(kv8-15,d8-15)
                uint32_t vb = (uint32_t)(16 * t + (lane & 7) + ((lane >> 3) & 1) * 8) * RPB
                            + (uint32_t)(32 * db) + (uint32_t)(lane >> 4) * 16;
                uint32_t vh[4], vl[4];
                ldm_x4_t(vh, sVhi + vb);
                ldm_x4_t(vl, sVlo + vb);
#pragma unroll
                for (int half = 0; half < 2; half++) {
                    int nt = 2 * db + half;
                    mma_bf16(o_[nt], pah, vh[2 * half], vh[2 * half + 1]);
                    mma_bf16(o_[nt], pah, vl[2 * half], vl[2 * half + 1]);
                    mma_bf16(o_[nt], pal, vh[2 * half], vh[2 * half + 1]);
                }
            }
        }
    }

    // ---- epilogue: normalize + write [B,N,DIM] ----
    const int rowA = q0 + 16 * wid + (lane >> 2);
    const int rowB = rowA + 8;
    const float invA = 1.f / lA, invB = 1.f / lB;
#pragma unroll
    for (int nt = 0; nt < 8; nt++) {
        int d0 = 8 * nt + 2 * (lane & 3);
        float2 vA = make_float2(o_[nt][0] * invA, o_[nt][1] * invA);
        float2 vB = make_float2(o_[nt][2] * invB, o_[nt][3] * invB);
        *(float2*)&out[((size_t)b * NN + rowA) * DIM + h * HD + d0] = vA;
        *(float2*)&out[((size_t)b * NN + rowB) * DIM + h * HD + d0] = vB;
    }
}

extern "C" void kernel_launch(void* const* d_in, const int* in_sizes, int n_in,
                              void* d_out, int out_size)
{
    (void)in_sizes; (void)n_in; (void)out_size;
    const float* x  = (const float*)d_in[0];
    const float* wq = (const float*)d_in[1];
    const float* bq = (const float*)d_in[2];
    const float* wk = (const float*)d_in[3];
    const float* bk = (const float*)d_in[4];
    const float* wv = (const float*)d_in[5];
    const float* bv = (const float*)d_in[6];
    float* out = (float*)d_out;

    size_t q_smem = 4 * (size_t)TILEB;   // 73728 B
    cudaFuncSetAttribute(qkv_mma, cudaFuncAttributeMaxDynamicSharedMemorySize,
                         (int)q_smem);
    dim3 g1(DIM / 128, MROWS / 128, 3);
    qkv_mma<<<g1, 256, q_smem>>>(x, wq, bq, wk, bk, wv, bv);

    size_t a_smem = 2 * (size_t)TILEB + 4 * (size_t)KTILEB;   // 73728 B
    cudaFuncSetAttribute(attn_mma, cudaFuncAttributeMaxDynamicSharedMemorySize,
                         (int)a_smem);
    dim3 g2(NN / 128, NH, BB);
    attn_mma<<<g2, 256, a_smem>>>(out);
}

// round 9
// speedup vs baseline: 3.8230x; 1.2412x over previous
#include <cuda_runtime.h>
#include <cuda_bf16.h>
#include <math.h>
#include <stdint.h>

#define BB 4
#define NN 2048
#define DIM 768
#define NH 12
#define HD 64
#define MROWS (BB*NN)   // 8192

// Scratch: q,k,v in [b,h,n,d] layout
__device__ float g_q[BB*NH*NN*HD];
__device__ float g_k[BB*NH*NN*HD];
__device__ float g_v[BB*NH*NN*HD];

// ====================== mma.sync helpers ======================
__device__ __forceinline__ uint32_t smem_u32(const void* p) {
    uint32_t a;
    asm("{ .reg .u64 t; cvta.to.shared.u64 t, %1; cvt.u32.u64 %0, t; }"
        : "=r"(a) : "l"(p));
    return a;
}
__device__ __forceinline__ void ldm_x4(uint32_t* r, uint32_t addr) {
    asm volatile("ldmatrix.sync.aligned.m8n8.x4.shared.b16 {%0,%1,%2,%3}, [%4];"
                 : "=r"(r[0]), "=r"(r[1]), "=r"(r[2]), "=r"(r[3]) : "r"(addr));
}
__device__ __forceinline__ void ldm_x4_t(uint32_t* r, uint32_t addr) {
    asm volatile("ldmatrix.sync.aligned.m8n8.x4.trans.shared.b16 {%0,%1,%2,%3}, [%4];"
                 : "=r"(r[0]), "=r"(r[1]), "=r"(r[2]), "=r"(r[3]) : "r"(addr));
}
__device__ __forceinline__ void mma_bf16(float* c, const uint32_t* a,
                                         uint32_t b0, uint32_t b1) {
    asm volatile(
        "mma.sync.aligned.m16n8k16.row.col.f32.bf16.bf16.f32 "
        "{%0,%1,%2,%3}, {%4,%5,%6,%7}, {%8,%9}, {%0,%1,%2,%3};"
        : "+f"(c[0]), "+f"(c[1]), "+f"(c[2]), "+f"(c[3])
        : "r"(a[0]), "r"(a[1]), "r"(a[2]), "r"(a[3]), "r"(b0), "r"(b1));
}
__device__ __forceinline__ uint32_t pk_bf2(__nv_bfloat16 a, __nv_bfloat16 b) {
    __nv_bfloat162 t(a, b);
    uint32_t u; *(__nv_bfloat162*)&u = t; return u;
}
// pack (lo elem, hi elem) -> bf16x2
__device__ __forceinline__ uint32_t pk_lohi(float lo, float hi) {
    uint32_t r;
    asm("cvt.rn.bf16x2.f32 %0, %1, %2;" : "=r"(r) : "f"(hi), "f"(lo));
    return r;
}
__device__ __forceinline__ float ex2f(float x) {
    float y;
    asm("ex2.approx.ftz.f32 %0, %1;" : "=f"(y) : "f"(x));
    return y;
}
__device__ __forceinline__ void cvt_hilo(float4 v, uint2& hi, uint2& lo) {
    __nv_bfloat16 h0 = __float2bfloat16(v.x), h1 = __float2bfloat16(v.y),
                  h2 = __float2bfloat16(v.z), h3 = __float2bfloat16(v.w);
    __nv_bfloat16 l0 = __float2bfloat16(v.x - __bfloat162float(h0));
    __nv_bfloat16 l1 = __float2bfloat16(v.y - __bfloat162float(h1));
    __nv_bfloat16 l2 = __float2bfloat16(v.z - __bfloat162float(h2));
    __nv_bfloat16 l3 = __float2bfloat16(v.w - __bfloat162float(h3));
    hi = make_uint2(pk_bf2(h0, h1), pk_bf2(h2, h3));
    lo = make_uint2(pk_bf2(l0, l1), pk_bf2(l2, l3));
}

#define RP  72
#define RPB 144
#define TILEB (128*RPB)           // 18432 B (128-row tile)
#define KTILEB (64*RPB)           // 9216 B  (64-row tile)

// ===================== QKV GEMM via mma.sync bf16 hi/lo =====================
#define CH 64

__global__ __launch_bounds__(256, 2) void qkv_mma(
    const float* __restrict__ x,
    const float* __restrict__ wq, const float* __restrict__ bq,
    const float* __restrict__ wk, const float* __restrict__ bk,
    const float* __restrict__ wv, const float* __restrict__ bv)
{
    extern __shared__ char smem[];
    char* Ahi = smem;
    char* Alo = Ahi + TILEB;
    char* Bhi = Alo + TILEB;
    char* Blo = Bhi + TILEB;
    const uint32_t sA_hi = smem_u32(Ahi);
    const uint32_t sA_lo = sA_hi + TILEB;
    const uint32_t sB_hi = sA_lo + TILEB;
    const uint32_t sB_lo = sB_hi + TILEB;

    const int mat = blockIdx.z;
    const float* w    = (mat == 0) ? wq : (mat == 1) ? wk : wv;
    const float* bias = (mat == 0) ? bq : (mat == 1) ? bk : bv;
    float* dst        = (mat == 0) ? g_q : (mat == 1) ? g_k : g_v;

    const int m0 = blockIdx.y * 128;
    const int o0 = blockIdx.x * 128;
    const int tid = threadIdx.x;
    const int wid = tid >> 5, lane = tid & 31;
    const int warpM = wid & 3, warpN = wid >> 2;
    const int m0w = warpM * 32, n0w = warpN * 64;
    const uint32_t lm_off = (uint32_t)(lane & 15) * RPB + (uint32_t)(lane >> 4) * 16;

    float acc[2][8][4];
#pragma unroll
    for (int mt = 0; mt < 2; mt++)
#pragma unroll
        for (int nt = 0; nt < 8; nt++)
#pragma unroll
            for (int q = 0; q < 4; q++) acc[mt][nt][q] = 0.f;

    for (int c = 0; c < DIM / CH; ++c) {
        const int kb = c * CH;
        __syncthreads();
#pragma unroll
        for (int p = 0; p < 8; ++p) {
            int e = tid + p * 256;
            int row = e >> 4, k4 = e & 15;
            uint32_t off = (uint32_t)(row * RPB + k4 * 8);
            uint2 hi, lo;
            cvt_hilo(*(const float4*)(x + (size_t)(m0 + row) * DIM + kb + 4 * k4), hi, lo);
            *(uint2*)(Ahi + off) = hi;
            *(uint2*)(Alo + off) = lo;
            cvt_hilo(*(const float4*)(w + (size_t)(o0 + row) * DIM + kb + 4 * k4), hi, lo);
            *(uint2*)(Bhi + off) = hi;
            *(uint2*)(Blo + off) = lo;
        }
        __syncthreads();

#pragma unroll
        for (int ks = 0; ks < 4; ++ks) {
            const uint32_t kso = (uint32_t)ks * 32;
            uint32_t a_hi[2][4], a_lo[2][4];
#pragma unroll
            for (int mt = 0; mt < 2; mt++) {
                uint32_t base = (uint32_t)(m0w + 16 * mt) * RPB + kso + lm_off;
                ldm_x4(a_hi[mt], sA_hi + base);
                ldm_x4(a_lo[mt], sA_lo + base);
            }
#pragma unroll
            for (int bp = 0; bp < 4; bp++) {
                uint32_t base = (uint32_t)(n0w + 16 * bp) * RPB + kso + lm_off;
                uint32_t b_hi[4], b_lo[4];
                ldm_x4(b_hi, sB_hi + base);
                ldm_x4(b_lo, sB_lo + base);
#pragma unroll
                for (int half = 0; half < 2; half++) {
                    int nt = 2 * bp + half;
#pragma unroll
                    for (int mt = 0; mt < 2; mt++) {
                        mma_bf16(acc[mt][nt], a_hi[mt], b_hi[half], b_hi[half + 2]);
                        mma_bf16(acc[mt][nt], a_hi[mt], b_lo[half], b_lo[half + 2]);
                        mma_bf16(acc[mt][nt], a_lo[mt], b_hi[half], b_hi[half + 2]);
                    }
                }
            }
        }
    }

#pragma unroll
    for (int mt = 0; mt < 2; mt++) {
#pragma unroll
        for (int nt = 0; nt < 8; nt++) {
            int row0 = m0 + m0w + 16 * mt + (lane >> 2);
            int col  = o0 + n0w + 8 * nt + 2 * (lane & 3);
            int h = col / HD, d = col & (HD - 1);
            float b0 = bias[col], b1 = bias[col + 1];
            {
                int b_ = row0 >> 11, n = row0 & (NN - 1);
                float2 v = make_float2(acc[mt][nt][0] + b0, acc[mt][nt][1] + b1);
                *(float2*)&dst[(((size_t)b_ * NH + h) * NN + n) * HD + d] = v;
            }
            {
                int row1 = row0 + 8;
                int b_ = row1 >> 11, n = row1 & (NN - 1);
                float2 v = make_float2(acc[mt][nt][2] + b0, acc[mt][nt][3] + b1);
                *(float2*)&dst[(((size_t)b_ * NH + h) * NN + n) * HD + d] = v;
            }
        }
    }
}

// ===================== Flash attention via mma.sync bf16 hi/lo =====================
// CTA: (b, h, 128 Q rows). 8 warps x 16 rows. KV tiles of 64.
__global__ __launch_bounds__(256, 2) void attn_mma(float* __restrict__ out)
{
    extern __shared__ char smem[];
    char* Qhi = smem;                   //  [128][RP] bf16
    char* Qlo = Qhi + TILEB;
    char* Khi = Qlo + TILEB;            //  [64][RP]
    char* Klo = Khi + KTILEB;
    char* Vhi = Klo + KTILEB;           //  [64][RP] natural [kv][d]
    char* Vlo = Vhi + KTILEB;
    const uint32_t sQhi = smem_u32(Qhi);
    const uint32_t sQlo = sQhi + TILEB;
    const uint32_t sKhi = sQlo + TILEB;
    const uint32_t sKlo = sKhi + KTILEB;
    const uint32_t sVhi = sKlo + KTILEB;
    const uint32_t sVlo = sVhi + KTILEB;

    const int b = blockIdx.z, h = blockIdx.y;
    const int q0 = blockIdx.x * 128;
    const size_t hb = ((size_t)b * NH + h) * NN;
    const float* qbase = g_q + hb * HD;
    const float* kbase = g_k + hb * HD;
    const float* vbase = g_v + hb * HD;

    const int tid = threadIdx.x;
    const int wid = tid >> 5, lane = tid & 31;
    const uint32_t lm_off = (uint32_t)(lane & 15) * RPB + (uint32_t)(lane >> 4) * 16;
    const float qsc = 0.125f * 1.44269504f;   // headdim^-0.5 * log2(e)

    // Load Q (scaled) -> hi/lo smem: 128x64, 8 float4/thread
#pragma unroll
    for (int p = 0; p < 8; ++p) {
        int e = tid + p * 256;
        int row = e >> 4, k4 = e & 15;
        float4 v = *(const float4*)(qbase + (size_t)(q0 + row) * HD + 4 * k4);
        v.x *= qsc; v.y *= qsc; v.z *= qsc; v.w *= qsc;
        uint2 hi, lo;
        cvt_hilo(v, hi, lo);
        uint32_t off = (uint32_t)(row * RPB + k4 * 8);
        *(uint2*)(Qhi + off) = hi;
        *(uint2*)(Qlo + off) = lo;
    }

    float o_[8][4];
    float mA = -INFINITY, mB = -INFINITY, lA = 0.f, lB = 0.f;
#pragma unroll
    for (int nt = 0; nt < 8; nt++)
#pragma unroll
        for (int q = 0; q < 4; q++) o_[nt][q] = 0.f;

    for (int j0 = 0; j0 < NN; j0 += 64) {
        __syncthreads();   // prior-iter V reads done before overwrite
#pragma unroll
        for (int p = 0; p < 4; ++p) {
            int e = tid + p * 256;
            int kv = e >> 4, d4 = e & 15;
            uint32_t off = (uint32_t)(kv * RPB + d4 * 8);
            uint2 hi, lo;
            cvt_hilo(*(const float4*)(kbase + (size_t)(j0 + kv) * HD + 4 * d4), hi, lo);
            *(uint2*)(Khi + off) = hi;
            *(uint2*)(Klo + off) = lo;
            cvt_hilo(*(const float4*)(vbase + (size_t)(j0 + kv) * HD + 4 * d4), hi, lo);
            *(uint2*)(Vhi + off) = hi;
            *(uint2*)(Vlo + off) = lo;
        }
        __syncthreads();

        // ---- S = Qs @ K^T (log2-domain logits), 3-term hi/lo ----
        float s_[8][4];
#pragma unroll
        for (int nt = 0; nt < 8; nt++)
#pragma unroll
            for (int q = 0; q < 4; q++) s_[nt][q] = 0.f;

#pragma unroll
        for (int ks = 0; ks < 4; ++ks) {
            const uint32_t kso = (uint32_t)ks * 32;
            uint32_t ah[4], al[4];
            uint32_t ab = (uint32_t)(wid * 16) * RPB + kso + lm_off;
            ldm_x4(ah, sQhi + ab);
            ldm_x4(al, sQlo + ab);
#pragma unroll
            for (int bp = 0; bp < 4; bp++) {
                uint32_t bb = (uint32_t)(16 * bp) * RPB + kso + lm_off;
                uint32_t bh[4], bl[4];
                ldm_x4(bh, sKhi + bb);
                ldm_x4(bl, sKlo + bb);
#pragma unroll
                for (int half = 0; half < 2; half++) {
                    int nt = 2 * bp + half;
                    mma_bf16(s_[nt], ah, bh[half], bh[half + 2]);
                    mma_bf16(s_[nt], ah, bl[half], bl[half + 2]);
                    mma_bf16(s_[nt], al, bh[half], bh[half + 2]);
                }
            }
        }

        // ---- online softmax (rows rA = lane>>2, rB = rA+8) ----
        float mlA = -INFINITY, mlB = -INFINITY;
#pragma unroll
        for (int nt = 0; nt < 8; nt++) {
            mlA = fmaxf(mlA, fmaxf(s_[nt][0], s_[nt][1]));
            mlB = fmaxf(mlB, fmaxf(s_[nt][2], s_[nt][3]));
        }
#pragma unroll
        for (int off = 1; off <= 2; off <<= 1) {
            mlA = fmaxf(mlA, __shfl_xor_sync(0xffffffffu, mlA, off));
            mlB = fmaxf(mlB, __shfl_xor_sync(0xffffffffu, mlB, off));
        }
        float mnA = fmaxf(mA, mlA), mnB = fmaxf(mB, mlB);
        float aAl = ex2f(mA - mnA), aBl = ex2f(mB - mnB);
        mA = mnA; mB = mnB;
        float sumA = 0.f, sumB = 0.f;
#pragma unroll
        for (int nt = 0; nt < 8; nt++) {
            s_[nt][0] = ex2f(s_[nt][0] - mA);
            s_[nt][1] = ex2f(s_[nt][1] - mA);
            s_[nt][2] = ex2f(s_[nt][2] - mB);
            s_[nt][3] = ex2f(s_[nt][3] - mB);
            sumA += s_[nt][0] + s_[nt][1];
            sumB += s_[nt][2] + s_[nt][3];
            o_[nt][0] *= aAl; o_[nt][1] *= aAl;
            o_[nt][2] *= aBl; o_[nt][3] *= aBl;
        }
#pragma unroll
        for (int off = 1; off <= 2; off <<= 1) {
            sumA += __shfl_xor_sync(0xffffffffu, sumA, off);
            sumB += __shfl_xor_sync(0xffffffffu, sumB, off);
        }
        lA = lA * aAl + sumA;
        lB = lB * aBl + sumB;

        // ---- O += P @ V : P repacked C-frag -> A-frag, V via ldmatrix.trans ----
#pragma unroll
        for (int t = 0; t < 4; t++) {
            uint32_t pah[4], pal[4];
#pragma unroll
            for (int i = 0; i < 4; i++) {
                const float* src = (i < 2) ? s_[2 * t] : s_[2 * t + 1];
                float x0 = src[(i & 1) ? 2 : 0];
                float x1 = src[(i & 1) ? 3 : 1];
                float h0 = __bfloat162float(__float2bfloat16(x0));
                float h1 = __bfloat162float(__float2bfloat16(x1));
                pah[i] = pk_lohi(h0, h1);
                pal[i] = pk_lohi(x0 - h0, x1 - h1);
            }
#pragma unroll
            for (int db = 0; db < 4; db++) {
                uint32_t vb = (uint32_t)(16 * t + (lane & 7) + ((lane >> 3) & 1) * 8) * RPB
                            + (uint32_t)(32 * db) + (uint32_t)(lane >> 4) * 16;
                uint32_t vh[4], vl[4];
                ldm_x4_t(vh, sVhi + vb);
                ldm_x4_t(vl, sVlo + vb);
#pragma unroll
                for (int half = 0; half < 2; half++) {
                    int nt = 2 * db + half;
                    mma_bf16(o_[nt], pah, vh[2 * half], vh[2 * half + 1]);
                    mma_bf16(o_[nt], pah, vl[2 * half], vl[2 * half + 1]);
                    mma_bf16(o_[nt], pal, vh[2 * half], vh[2 * half + 1]);
                }
            }
        }
    }

    // ---- epilogue: normalize + write [B,N,DIM] ----
    const int rowA = q0 + 16 * wid + (lane >> 2);
    const int rowB = rowA + 8;
    const float invA = 1.f / lA, invB = 1.f / lB;
#pragma unroll
    for (int nt = 0; nt < 8; nt++) {
        int d0 = 8 * nt + 2 * (lane & 3);
        float2 vA = make_float2(o_[nt][0] * invA, o_[nt][1] * invA);
        float2 vB = make_float2(o_[nt][2] * invB, o_[nt][3] * invB);
        *(float2*)&out[((size_t)b * NN + rowA) * DIM + h * HD + d0] = vA;
        *(float2*)&out[((size_t)b * NN + rowB) * DIM + h * HD + d0] = vB;
    }
}

extern "C" void kernel_launch(void* const* d_in, const int* in_sizes, int n_in,
                              void* d_out, int out_size)
{
    (void)in_sizes; (void)n_in; (void)out_size;
    const float* x  = (const float*)d_in[0];
    const float* wq = (const float*)d_in[1];
    const float* bq = (const float*)d_in[2];
    const float* wk = (const float*)d_in[3];
    const float* bk = (const float*)d_in[4];
    const float* wv = (const float*)d_in[5];
    const float* bv = (const float*)d_in[6];
    float* out = (float*)d_out;

    size_t q_smem = 4 * (size_t)TILEB;   // 73728 B
    cudaFuncSetAttribute(qkv_mma, cudaFuncAttributeMaxDynamicSharedMemorySize,
                         (int)q_smem);
    dim3 g1(DIM / 128, MROWS / 128, 3);
    qkv_mma<<<g1, 256, q_smem>>>(x, wq, bq, wk, bk, wv, bv);

    size_t a_smem = 2 * (size_t)TILEB + 4 * (size_t)KTILEB;   // 73728 B
    cudaFuncSetAttribute(attn_mma, cudaFuncAttributeMaxDynamicSharedMemorySize,
                         (int)a_smem);
    dim3 g2(NN / 128, NH, BB);
    attn_mma<<<g2, 256, a_smem>>>(out);
}

// round 11
// speedup vs baseline: 3.8797x; 1.0148x over previous
#include <cuda_runtime.h>
#include <cuda_bf16.h>
#include <math.h>
#include <stdint.h>

#define BB 4
#define NN 2048
#define DIM 768
#define NH 12
#define HD 64
#define MROWS (BB*NN)   // 8192
#define SZT (BB*NH*NN*HD)

// Scratch: q,k,v as bf16 hi/lo pairs, [b,h,n,d] layout (12.6 MB each)
__device__ __align__(16) __nv_bfloat16 g_qh[SZT], g_ql[SZT];
__device__ __align__(16) __nv_bfloat16 g_kh[SZT], g_kl[SZT];
__device__ __align__(16) __nv_bfloat16 g_vh[SZT], g_vl[SZT];

// ====================== helpers ======================
__device__ __forceinline__ uint32_t smem_u32(const void* p) {
    uint32_t a;
    asm("{ .reg .u64 t; cvta.to.shared.u64 t, %1; cvt.u32.u64 %0, t; }"
        : "=r"(a) : "l"(p));
    return a;
}
__device__ __forceinline__ void ldm_x4(uint32_t* r, uint32_t addr) {
    asm volatile("ldmatrix.sync.aligned.m8n8.x4.shared.b16 {%0,%1,%2,%3}, [%4];"
                 : "=r"(r[0]), "=r"(r[1]), "=r"(r[2]), "=r"(r[3]) : "r"(addr));
}
__device__ __forceinline__ void ldm_x4_t(uint32_t* r, uint32_t addr) {
    asm volatile("ldmatrix.sync.aligned.m8n8.x4.trans.shared.b16 {%0,%1,%2,%3}, [%4];"
                 : "=r"(r[0]), "=r"(r[1]), "=r"(r[2]), "=r"(r[3]) : "r"(addr));
}
__device__ __forceinline__ void mma_bf16(float* c, const uint32_t* a,
                                         uint32_t b0, uint32_t b1) {
    asm volatile(
        "mma.sync.aligned.m16n8k16.row.col.f32.bf16.bf16.f32 "
        "{%0,%1,%2,%3}, {%4,%5,%6,%7}, {%8,%9}, {%0,%1,%2,%3};"
        : "+f"(c[0]), "+f"(c[1]), "+f"(c[2]), "+f"(c[3])
        : "r"(a[0]), "r"(a[1]), "r"(a[2]), "r"(a[3]), "r"(b0), "r"(b1));
}
__device__ __forceinline__ uint32_t pk_bf2(__nv_bfloat16 a, __nv_bfloat16 b) {
    __nv_bfloat162 t(a, b);
    uint32_t u; *(__nv_bfloat162*)&u = t; return u;
}
__device__ __forceinline__ uint32_t pk_lohi(float lo, float hi) {
    uint32_t r;
    asm("cvt.rn.bf16x2.f32 %0, %1, %2;" : "=r"(r) : "f"(hi), "f"(lo));
    return r;
}
__device__ __forceinline__ float ex2f(float x) {
    float y;
    asm("ex2.approx.ftz.f32 %0, %1;" : "=f"(y) : "f"(x));
    return y;
}
__device__ __forceinline__ void cvt_hilo(float4 v, uint2& hi, uint2& lo) {
    __nv_bfloat16 h0 = __float2bfloat16(v.x), h1 = __float2bfloat16(v.y),
                  h2 = __float2bfloat16(v.z), h3 = __float2bfloat16(v.w);
    __nv_bfloat16 l0 = __float2bfloat16(v.x - __bfloat162float(h0));
    __nv_bfloat16 l1 = __float2bfloat16(v.y - __bfloat162float(h1));
    __nv_bfloat16 l2 = __float2bfloat16(v.z - __bfloat162float(h2));
    __nv_bfloat16 l3 = __float2bfloat16(v.w - __bfloat162float(h3));
    hi = make_uint2(pk_bf2(h0, h1), pk_bf2(h2, h3));
    lo = make_uint2(pk_bf2(l0, l1), pk_bf2(l2, l3));
}
__device__ __forceinline__ void st_hilo(__nv_bfloat16* dh, __nv_bfloat16* dl,
                                        float v0, float v1) {
    __nv_bfloat16 h0 = __float2bfloat16(v0), h1 = __float2bfloat16(v1);
    __nv_bfloat16 l0 = __float2bfloat16(v0 - __bfloat162float(h0));
    __nv_bfloat16 l1 = __float2bfloat16(v1 - __bfloat162float(h1));
    *(uint32_t*)dh = pk_bf2(h0, h1);
    *(uint32_t*)dl = pk_bf2(l0, l1);
}
__device__ __forceinline__ void cpa16(uint32_t s, const void* g) {
    asm volatile("cp.async.cg.shared.global [%0], [%1], 16;"
                 :: "r"(s), "l"(g) : "memory");
}
#define CPA_COMMIT() asm volatile("cp.async.commit_group;" ::: "memory")
#define CPA_WAIT0()  asm volatile("cp.async.wait_group 0;" ::: "memory")

#define RP  72
#define RPB 144
#define TILEB (128*RPB)           // 18432 B (128-row tile)
#define KTILEB (64*RPB)           // 9216 B  (64-row tile)
#define KSTG (4*KTILEB)           // Khi,Klo,Vhi,Vlo per stage

// ===================== QKV GEMM via mma.sync bf16 hi/lo =====================
#define CH 64

__global__ __launch_bounds__(256, 2) void qkv_mma(
    const float* __restrict__ x,
    const float* __restrict__ wq, const float* __restrict__ bq,
    const float* __restrict__ wk, const float* __restrict__ bk,
    const float* __restrict__ wv, const float* __restrict__ bv)
{
    extern __shared__ char smem[];
    char* Ahi = smem;
    char* Alo = Ahi + TILEB;
    char* Bhi = Alo + TILEB;
    char* Blo = Bhi + TILEB;
    const uint32_t sA_hi = smem_u32(Ahi);
    const uint32_t sA_lo = sA_hi + TILEB;
    const uint32_t sB_hi = sA_lo + TILEB;
    const uint32_t sB_lo = sB_hi + TILEB;

    const int mat = blockIdx.z;
    const float* w    = (mat == 0) ? wq : (mat == 1) ? wk : wv;
    const float* bias = (mat == 0) ? bq : (mat == 1) ? bk : bv;
    __nv_bfloat16* dh = (mat == 0) ? g_qh : (mat == 1) ? g_kh : g_vh;
    __nv_bfloat16* dl = (mat == 0) ? g_ql : (mat == 1) ? g_kl : g_vl;

    const int m0 = blockIdx.y * 128;
    const int o0 = blockIdx.x * 128;
    const int tid = threadIdx.x;
    const int wid = tid >> 5, lane = tid & 31;
    const int warpM = wid & 3, warpN = wid >> 2;
    const int m0w = warpM * 32, n0w = warpN * 64;
    const uint32_t lm_off = (uint32_t)(lane & 15) * RPB + (uint32_t)(lane >> 4) * 16;

    float acc[2][8][4];
#pragma unroll
    for (int mt = 0; mt < 2; mt++)
#pragma unroll
        for (int nt = 0; nt < 8; nt++)
#pragma unroll
            for (int q = 0; q < 4; q++) acc[mt][nt][q] = 0.f;

    for (int c = 0; c < DIM / CH; ++c) {
        const int kb = c * CH;
        __syncthreads();
#pragma unroll
        for (int p = 0; p < 8; ++p) {
            int e = tid + p * 256;
            int row = e >> 4, k4 = e & 15;
            uint32_t off = (uint32_t)(row * RPB + k4 * 8);
            uint2 hi, lo;
            cvt_hilo(*(const float4*)(x + (size_t)(m0 + row) * DIM + kb + 4 * k4), hi, lo);
            *(uint2*)(Ahi + off) = hi;
            *(uint2*)(Alo + off) = lo;
            cvt_hilo(*(const float4*)(w + (size_t)(o0 + row) * DIM + kb + 4 * k4), hi, lo);
            *(uint2*)(Bhi + off) = hi;
            *(uint2*)(Blo + off) = lo;
        }
        __syncthreads();

#pragma unroll
        for (int ks = 0; ks < 4; ++ks) {
            const uint32_t kso = (uint32_t)ks * 32;
            uint32_t a_hi[2][4], a_lo[2][4];
#pragma unroll
            for (int mt = 0; mt < 2; mt++) {
                uint32_t base = (uint32_t)(m0w + 16 * mt) * RPB + kso + lm_off;
                ldm_x4(a_hi[mt], sA_hi + base);
                ldm_x4(a_lo[mt], sA_lo + base);
            }
#pragma unroll
            for (int bp = 0; bp < 4; bp++) {
                uint32_t base = (uint32_t)(n0w + 16 * bp) * RPB + kso + lm_off;
                uint32_t b_hi[4], b_lo[4];
                ldm_x4(b_hi, sB_hi + base);
                ldm_x4(b_lo, sB_lo + base);
#pragma unroll
                for (int half = 0; half < 2; half++) {
                    int nt = 2 * bp + half;
#pragma unroll
                    for (int mt = 0; mt < 2; mt++) {
                        mma_bf16(acc[mt][nt], a_hi[mt], b_hi[half], b_hi[half + 2]);
                        mma_bf16(acc[mt][nt], a_hi[mt], b_lo[half], b_lo[half + 2]);
                        mma_bf16(acc[mt][nt], a_lo[mt], b_hi[half], b_hi[half + 2]);
                    }
                }
            }
        }
    }

    // Epilogue: bias add + hi/lo split + head-split store
#pragma unroll
    for (int mt = 0; mt < 2; mt++) {
#pragma unroll
        for (int nt = 0; nt < 8; nt++) {
            int row0 = m0 + m0w + 16 * mt + (lane >> 2);
            int col  = o0 + n0w + 8 * nt + 2 * (lane & 3);
            int h = col / HD, d = col & (HD - 1);
            float b0 = bias[col], b1 = bias[col + 1];
            {
                int b_ = row0 >> 11, n = row0 & (NN - 1);
                size_t idx = (((size_t)b_ * NH + h) * NN + n) * HD + d;
                st_hilo(dh + idx, dl + idx, acc[mt][nt][0] + b0, acc[mt][nt][1] + b1);
            }
            {
                int row1 = row0 + 8;
                int b_ = row1 >> 11, n = row1 & (NN - 1);
                size_t idx = (((size_t)b_ * NH + h) * NN + n) * HD + d;
                st_hilo(dh + idx, dl + idx, acc[mt][nt][2] + b0, acc[mt][nt][3] + b1);
            }
        }
    }
}

// ===================== Flash attention: cp.async double-buffered =====================
// CTA: (b, h, 128 Q rows). 8 warps x 16 rows. KV tiles of 64, 2 smem stages.
__global__ __launch_bounds__(256, 2) void attn_mma(float* __restrict__ out)
{
    extern __shared__ char smem[];
    const uint32_t sbase = smem_u32(smem);
    const uint32_t sQhi = sbase;
    const uint32_t sQlo = sbase + TILEB;
    const uint32_t sKV0 = sbase + 2 * TILEB;     // stage st: sKV0 + st*KSTG

    const int b = blockIdx.z, h = blockIdx.y;
    const int q0 = blockIdx.x * 128;
    const size_t hb = ((size_t)b * NH + h) * NN;
    const __nv_bfloat16* qh = g_qh + hb * HD;
    const __nv_bfloat16* ql = g_ql + hb * HD;
    const __nv_bfloat16* kh = g_kh + hb * HD;
    const __nv_bfloat16* kl = g_kl + hb * HD;
    const __nv_bfloat16* vh = g_vh + hb * HD;
    const __nv_bfloat16* vl = g_vl + hb * HD;

    const int tid = threadIdx.x;
    const int wid = tid >> 5, lane = tid & 31;
    const uint32_t lm_off = (uint32_t)(lane & 15) * RPB + (uint32_t)(lane >> 4) * 16;
    const float qsc = 0.125f * 1.44269504f;   // headdim^-0.5 * log2(e)
    const int seg = tid & 7;                  // 16B segment within 128B row
    const int rbase = tid >> 3;               // 0..31

    // ---- issue tile 0 (cp.async), then plain-copy Q ----
    {
#pragma unroll
        for (int p = 0; p < 8; ++p) {
            const int arr = p >> 1;           // 0=Khi 1=Klo 2=Vhi 3=Vlo
            int r = (p & 1) * 32 + rbase;
            const __nv_bfloat16* g = (arr == 0) ? kh : (arr == 1) ? kl
                                   : (arr == 2) ? vh : vl;
            uint32_t sdst = sKV0 + (uint32_t)(arr * KTILEB + r * RPB + seg * 16);
            cpa16(sdst, g + (size_t)r * HD + seg * 8);
        }
        CPA_COMMIT();
    }
#pragma unroll
    for (int p = 0; p < 8; ++p) {             // Q: 2 arrays x 128 rows x 8 seg
        const int arr = p >> 2;               // 0=Qhi 1=Qlo
        int r = (p & 3) * 32 + rbase;
        const __nv_bfloat16* g = arr ? ql : qh;
        uint4 v = *(const uint4*)(g + (size_t)(q0 + r) * HD + seg * 8);
        *(uint4*)(smem + (arr ? TILEB : 0) + r * RPB + seg * 16) = v;
    }

    float o_[8][4];
    float mA = -INFINITY, mB = -INFINITY, lA = 0.f, lB = 0.f;
#pragma unroll
    for (int nt = 0; nt < 8; nt++)
#pragma unroll
        for (int q = 0; q < 4; q++) o_[nt][q] = 0.f;

    const int NT = NN / 64;   // 32 tiles
    for (int it = 0; it < NT; ++it) {
        const int st = it & 1;
        CPA_WAIT0();
        __syncthreads();      // tile it visible; all warps done with stage st (from it-2)

        if (it + 1 < NT) {    // prefetch tile it+1 into the other stage
            const int j1 = (it + 1) * 64;
            const uint32_t sst = sKV0 + (uint32_t)(((it + 1) & 1) * KSTG);
#pragma unroll
            for (int p = 0; p < 8; ++p) {
                const int arr = p >> 1;
                int r = (p & 1) * 32 + rbase;
                const __nv_bfloat16* g = (arr == 0) ? kh : (arr == 1) ? kl
                                       : (arr == 2) ? vh : vl;
                uint32_t sdst = sst + (uint32_t)(arr * KTILEB + r * RPB + seg * 16);
                cpa16(sdst, g + (size_t)(j1 + r) * HD + seg * 8);
            }
            CPA_COMMIT();
        }

        const uint32_t sKhi = sKV0 + (uint32_t)(st * KSTG);
        const uint32_t sKlo = sKhi + KTILEB;
        const uint32_t sVhi = sKlo + KTILEB;
        const uint32_t sVlo = sVhi + KTILEB;

        // ---- S = Q @ K^T, 3-term hi/lo ----
        float s_[8][4];
#pragma unroll
        for (int nt = 0; nt < 8; nt++)
#pragma unroll
            for (int q = 0; q < 4; q++) s_[nt][q] = 0.f;

#pragma unroll
        for (int ks = 0; ks < 4; ++ks) {
            const uint32_t kso = (uint32_t)ks * 32;
            uint32_t ah[4], al[4];
            uint32_t ab = (uint32_t)(wid * 16) * RPB + kso + lm_off;
            ldm_x4(ah, sQhi + ab);
            ldm_x4(al, sQlo + ab);
#pragma unroll
            for (int bp = 0; bp < 4; bp++) {
                uint32_t bb = (uint32_t)(16 * bp) * RPB + kso + lm_off;
                uint32_t bh[4], bl[4];
                ldm_x4(bh, sKhi + bb);
                ldm_x4(bl, sKlo + bb);
#pragma unroll
                for (int half = 0; half < 2; half++) {
                    int nt = 2 * bp + half;
                    mma_bf16(s_[nt], ah, bh[half], bh[half + 2]);
                    mma_bf16(s_[nt], ah, bl[half], bl[half + 2]);
                    mma_bf16(s_[nt], al, bh[half], bh[half + 2]);
                }
            }
        }

        // ---- scale to log2 domain + online softmax ----
        float mlA = -INFINITY, mlB = -INFINITY;
#pragma unroll
        for (int nt = 0; nt < 8; nt++) {
            s_[nt][0] *= qsc; s_[nt][1] *= qsc;
            s_[nt][2] *= qsc; s_[nt][3] *= qsc;
            mlA = fmaxf(mlA, fmaxf(s_[nt][0], s_[nt][1]));
            mlB = fmaxf(mlB, fmaxf(s_[nt][2], s_[nt][3]));
        }
#pragma unroll
        for (int off = 1; off <= 2; off <<= 1) {
            mlA = fmaxf(mlA, __shfl_xor_sync(0xffffffffu, mlA, off));
            mlB = fmaxf(mlB, __shfl_xor_sync(0xffffffffu, mlB, off));
        }
        float mnA = fmaxf(mA, mlA), mnB = fmaxf(mB, mlB);
        float aAl = ex2f(mA - mnA), aBl = ex2f(mB - mnB);
        mA = mnA; mB = mnB;
        float sumA = 0.f, sumB = 0.f;
#pragma unroll
        for (int nt = 0; nt < 8; nt++) {
            s_[nt][0] = ex2f(s_[nt][0] - mA);
            s_[nt][1] = ex2f(s_[nt][1] - mA);
            s_[nt][2] = ex2f(s_[nt][2] - mB);
            s_[nt][3] = ex2f(s_[nt][3] - mB);
            sumA += s_[nt][0] + s_[nt][1];
            sumB += s_[nt][2] + s_[nt][3];
            o_[nt][0] *= aAl; o_[nt][1] *= aAl;
            o_[nt][2] *= aBl; o_[nt][3] *= aBl;
        }
#pragma unroll
        for (int off = 1; off <= 2; off <<= 1) {
            sumA += __shfl_xor_sync(0xffffffffu, sumA, off);
            sumB += __shfl_xor_sync(0xffffffffu, sumB, off);
        }
        lA = lA * aAl + sumA;
        lB = lB * aBl + sumB;

        // ---- O += P @ V : P C-frag -> A-frag repack, V via ldmatrix.trans ----
#pragma unroll
        for (int t = 0; t < 4; t++) {
            uint32_t pah[4], pal[4];
#pragma unroll
            for (int i = 0; i < 4; i++) {
                const float* src = (i < 2) ? s_[2 * t] : s_[2 * t + 1];
                float x0 = src[(i & 1) ? 2 : 0];
                float x1 = src[(i & 1) ? 3 : 1];
                float h0 = __bfloat162float(__float2bfloat16(x0));
                float h1 = __bfloat162float(__float2bfloat16(x1));
                pah[i] = pk_lohi(h0, h1);
                pal[i] = pk_lohi(x0 - h0, x1 - h1);
            }
#pragma unroll
            for (int db = 0; db < 4; db++) {
                uint32_t vb = (uint32_t)(16 * t + (lane & 7) + ((lane >> 3) & 1) * 8) * RPB
                            + (uint32_t)(32 * db) + (uint32_t)(lane >> 4) * 16;
                uint32_t vhf[4], vlf[4];
                ldm_x4_t(vhf, sVhi + vb);
                ldm_x4_t(vlf, sVlo + vb);
#pragma unroll
                for (int half = 0; half < 2; half++) {
                    int nt = 2 * db + half;
                    mma_bf16(o_[nt], pah, vhf[2 * half], vhf[2 * half + 1]);
                    mma_bf16(o_[nt], pah, vlf[2 * half], vlf[2 * half + 1]);
                    mma_bf16(o_[nt], pal, vhf[2 * half], vhf[2 * half + 1]);
                }
            }
        }
    }

    // ---- epilogue: normalize + write [B,N,DIM] ----
    const int rowA = q0 + 16 * wid + (lane >> 2);
    const int rowB = rowA + 8;
    const float invA = 1.f / lA, invB = 1.f / lB;
#pragma unroll
    for (int nt = 0; nt < 8; nt++) {
        int d0 = 8 * nt + 2 * (lane & 3);
        float2 vA = make_float2(o_[nt][0] * invA, o_[nt][1] * invA);
        float2 vB = make_float2(o_[nt][2] * invB, o_[nt][3] * invB);
        *(float2*)&out[((size_t)b * NN + rowA) * DIM + h * HD + d0] = vA;
        *(float2*)&out[((size_t)b * NN + rowB) * DIM + h * HD + d0] = vB;
    }
}

extern "C" void kernel_launch(void* const* d_in, const int* in_sizes, int n_in,
                              void* d_out, int out_size)
{
    (void)in_sizes; (void)n_in; (void)out_size;
    const float* x  = (const float*)d_in[0];
    const float* wq = (const float*)d_in[1];
    const float* bq = (const float*)d_in[2];
    const float* wk = (const float*)d_in[3];
    const float* bk = (const float*)d_in[4];
    const float* wv = (const float*)d_in[5];
    const float* bv = (const float*)d_in[6];
    float* out = (float*)d_out;

    size_t q_smem = 4 * (size_t)TILEB;   // 73728 B
    cudaFuncSetAttribute(qkv_mma, cudaFuncAttributeMaxDynamicSharedMemorySize,
                         (int)q_smem);
    dim3 g1(DIM / 128, MROWS / 128, 3);
    qkv_mma<<<g1, 256, q_smem>>>(x, wq, bq, wk, bk, wv, bv);

    size_t a_smem = 2 * (size_t)TILEB + 2 * (size_t)KSTG;   // 110592 B
    cudaFuncSetAttribute(attn_mma, cudaFuncAttributeMaxDynamicSharedMemorySize,
                         (int)a_smem);
    dim3 g2(NN / 128, NH, BB);
    attn_mma<<<g2, 256, a_smem>>>(out);
}